// round 2
// baseline (speedup 1.0000x reference)
#include <cuda_runtime.h>
#include <cstdint>

// Problem constants
#define NBATCH   32
#define C_DIM    256
#define HWDIM    64
#define PIX_PER_N (HWDIM * HWDIM)      // 4096
#define K_CLUST  128
#define OUT_BINS (K_CLUST + 1)         // 129
#define S_SIDE   8
#define BLOCKSZ  8                      // 8x8 spatial blocks, 64 px each

// GEMM tiling
#define TILE_P   128                    // pixels per CTA
#define TILE_C   16                     // channel chunk
#define NTHREADS 256

__device__ float g_c2[K_CLUST];

// --- tiny kernel: c2[k] = ||center_k||^2 ---
__global__ void c2_kernel(const float* __restrict__ centers) {
    int k = threadIdx.x;
    if (k >= K_CLUST) return;
    const float* row = centers + (size_t)k * C_DIM;
    float s = 0.f;
#pragma unroll 8
    for (int c = 0; c < C_DIM; ++c) s = fmaf(row[c], row[c], s);
    g_c2[k] = s;
}

// --- main kernel: per-pixel argmin over clusters + histogram scatter ---
__global__ __launch_bounds__(NTHREADS, 2)
void vq_hist_kernel(const float* __restrict__ x,
                    const float* __restrict__ centers,
                    float* __restrict__ out) {
    // As[c][p]: x tile (16 x 128), Bs[c][k]: center tile transposed (16 x 128)
    __shared__ float As[TILE_C][TILE_P];
    __shared__ float Bs[TILE_C][K_CLUST];

    const int tid = threadIdx.x;
    const int ct  = blockIdx.x;               // 0..1023
    const int n   = ct >> 5;                  // 32 pixel-tiles per batch image
    const int p0  = (ct & 31) * TILE_P;

    const float* xn = x + (size_t)n * C_DIM * PIX_PER_N + p0;

    const int tx = tid & 15;                  // cluster group: k = tx*8..tx*8+7
    const int ty = tid >> 4;                  // pixel group:   p = ty*8..ty*8+7

    float acc[8][8];
#pragma unroll
    for (int i = 0; i < 8; ++i)
#pragma unroll
        for (int j = 0; j < 8; ++j) acc[i][j] = 0.f;

    for (int kc = 0; kc < C_DIM; kc += TILE_C) {
        __syncthreads();   // previous compute done before overwriting tiles
        // load As: 16 rows x 128 floats = 512 float4; 2 per thread, coalesced
#pragma unroll
        for (int i = 0; i < 2; ++i) {
            int q   = tid + NTHREADS * i;     // 0..511
            int row = q >> 5;                 // 0..15
            int col = (q & 31) << 2;          // 0..124 step 4
            float4 v = *reinterpret_cast<const float4*>(
                xn + (size_t)(kc + row) * PIX_PER_N + col);
            *reinterpret_cast<float4*>(&As[row][col]) = v;
        }
        // load Bs (transpose): 128 k x 16 c = 512 float4 reads
#pragma unroll
        for (int i = 0; i < 2; ++i) {
            int q  = tid + NTHREADS * i;      // 0..511
            int k  = q >> 2;                  // 0..127
            int c4 = (q & 3) << 2;            // 0,4,8,12
            float4 v = *reinterpret_cast<const float4*>(
                centers + (size_t)k * C_DIM + kc + c4);
            Bs[c4 + 0][k] = v.x;
            Bs[c4 + 1][k] = v.y;
            Bs[c4 + 2][k] = v.z;
            Bs[c4 + 3][k] = v.w;
        }
        __syncthreads();

#pragma unroll
        for (int cc = 0; cc < TILE_C; ++cc) {
            float4 a0 = *reinterpret_cast<const float4*>(&As[cc][ty * 8]);
            float4 a1 = *reinterpret_cast<const float4*>(&As[cc][ty * 8 + 4]);
            float4 b0 = *reinterpret_cast<const float4*>(&Bs[cc][tx * 8]);
            float4 b1 = *reinterpret_cast<const float4*>(&Bs[cc][tx * 8 + 4]);
            float a[8] = {a0.x, a0.y, a0.z, a0.w, a1.x, a1.y, a1.z, a1.w};
            float b[8] = {b0.x, b0.y, b0.z, b0.w, b1.x, b1.y, b1.z, b1.w};
#pragma unroll
            for (int i = 0; i < 8; ++i)
#pragma unroll
                for (int j = 0; j < 8; ++j)
                    acc[i][j] = fmaf(a[i], b[j], acc[i][j]);
        }
    }

    // ---- epilogue: per-pixel argmin of (c2[k] - 2*dot) ----
    float c2v[8];
#pragma unroll
    for (int j = 0; j < 8; ++j) c2v[j] = g_c2[tx * 8 + j];

    float best[8];
    int   bidx[8];
#pragma unroll
    for (int i = 0; i < 8; ++i) {
        float s0 = fmaf(-2.f, acc[i][0], c2v[0]);
        best[i] = s0;
        bidx[i] = tx * 8;
#pragma unroll
        for (int j = 1; j < 8; ++j) {
            float s = fmaf(-2.f, acc[i][j], c2v[j]);
            if (s < best[i]) { best[i] = s; bidx[i] = tx * 8 + j; }  // strict < keeps lowest k
        }
    }

    __syncthreads();
    // reuse As/Bs smem as [pixel][16] score / idx arrays
    float* sS = &As[0][0];                    // 128*16 floats
    int*   sI = reinterpret_cast<int*>(&Bs[0][0]);
#pragma unroll
    for (int i = 0; i < 8; ++i) {
        int p = ty * 8 + i;
        sS[p * 16 + tx] = best[i];
        sI[p * 16 + tx] = bidx[i];
    }
    __syncthreads();

    if (tid < TILE_P) {
        int p_local = tid;
        float bs = sS[p_local * 16 + 0];
        int   bi = sI[p_local * 16 + 0];
#pragma unroll
        for (int t = 1; t < 16; ++t) {
            float s = sS[p_local * 16 + t];
            int   k = sI[p_local * 16 + t];
            if (s < bs || (s == bs && k < bi)) { bs = s; bi = k; }
        }
        int p_global = p0 + p_local;          // pixel index within batch image
        int h = p_global >> 6;
        int w = p_global & 63;
        int sblk = (h >> 3) * S_SIDE + (w >> 3);
        int code = bi + 1;                    // shifted code in [1, K]
        atomicAdd(&out[((size_t)n * (S_SIDE * S_SIDE) + sblk) * OUT_BINS + code],
                  1.0f / (BLOCKSZ * BLOCKSZ));
    }
}

extern "C" void kernel_launch(void* const* d_in, const int* in_sizes, int n_in,
                              void* d_out, int out_size) {
    const float* x       = (const float*)d_in[0];
    const float* centers = (const float*)d_in[1];
    float* out           = (float*)d_out;

    // output is poisoned; histogram accumulates, so zero it first
    cudaMemsetAsync(d_out, 0, (size_t)out_size * sizeof(float), 0);

    c2_kernel<<<1, K_CLUST>>>(centers);

    int nblocks = (NBATCH * PIX_PER_N) / TILE_P;   // 1024
    vq_hist_kernel<<<nblocks, NTHREADS>>>(x, centers, out);
}